// round 10
// baseline (speedup 1.0000x reference)
#include <cuda_runtime.h>
#include <math.h>

#define WDIM 512
#define LDIM 512
#define WL   (WDIM * LDIM)      // 262144 pixels
#define NTGT 64
#define TPB  256
// tile = 16 rows x 64 cols; each thread handles 4 adjacent-j pixels
#define NBLK 256                // 32 i-tiles x 8 j-tiles

__device__ float        g_accum;  // zero-init; last block resets
__device__ unsigned int g_done;   // zero-init; last block resets

// logit(0.1) = ln(0.1/0.9)
#define LOGIT_THRESH (-2.1972245773362196f)

__device__ __forceinline__ float f4c(const float4 v, int p) {
    return (p == 0) ? v.x : (p == 1) ? v.y : (p == 2) ? v.z : v.w;
}

// ---------------------------------------------------------------------------
// Single kernel. 4 pixels x 2 anchors per thread; all streaming loads are
// LDG.128 (float4) to maximize bytes-in-flight per warp. Anchor grid is
// reconstructed from a few uniform loads (separable regular grid).
// ---------------------------------------------------------------------------
__global__ __launch_bounds__(TPB, 2) void loss_kernel(
    const float* __restrict__ psm,    // [2, W, L]
    const float* __restrict__ rm,     // [14, W, L]
    const float* __restrict__ anc,    // [W, L, 2, 7]
    const float* __restrict__ Tm,     // [4, 4]
    const float* __restrict__ target, // [64, 7]
    float* __restrict__ out)
{
    const int tid = threadIdx.x;

    // ---- tile -> pixel-quad mapping ----
    const int tile_i = blockIdx.x >> 3;            // 0..31
    const int tile_j = blockIdx.x & 7;             // 0..7
    const int i  = tile_i * 16 + (tid >> 4);       // row
    const int jq = tile_j * 16 + (tid & 15);       // quad index
    const int pix0 = i * LDIM + jq * 4;            // 16B-aligned

    // ---- front-batch all streaming loads: 16 x LDG.128 per thread ----
    float4 rc[14];
#pragma unroll
    for (int c = 0; c < 14; c++)
        rc[c] = *(const float4*)(rm + (size_t)c * WL + pix0);

    const float4 sA = *(const float4*)(psm + pix0);       // anchor 0, 4 px
    const float4 sB = *(const float4*)(psm + WL + pix0);  // anchor 1, 4 px

    // ---- anchor grid parameters (uniform loads, cached) ----
    const float x0   = anc[0];
    const float y0   = anc[1];
    const float cz   = anc[2];
    const float ah   = anc[3];
    const float aw   = anc[4];
    const float al   = anc[5];
    const float yaw0 = anc[6];
    const float yaw1 = anc[13];
    const float dxs  = anc[512 * 14] - x0;     // xs step (pixel (1,0))
    const float dys  = anc[14 + 1]   - y0;     // ys step (pixel (0,1))

    const float dg = sqrtf(aw * aw + al * al);
    const float ax = fmaf((float)i, dxs, x0);

    // ---- target standup boxes (threads 0..63) ----
    float tminx = 0.f, tminy = 0.f, tmaxx = 0.f, tmaxy = 0.f, tarea = 0.f;
    if (tid < NTGT) {
        const float* t = target + tid * 7;
        float X = t[0], Y = t[1];
        float w = t[4], l = t[5];
        float c, s;
        __sincosf(t[6], &s, &c);
        float ex = 0.5f * (fabsf(c) * l + fabsf(s) * w);
        float ey = 0.5f * (fabsf(s) * l + fabsf(c) * w);
        tminx = X - ex;  tmaxx = X + ex;
        tminy = Y - ey;  tmaxy = Y + ey;
        tarea = (2.0f * ex) * (2.0f * ey);
    }

    const float T00 = Tm[0], T01 = Tm[1], T02 = Tm[2], T03 = Tm[3];
    const float T10 = Tm[4], T11 = Tm[5], T12 = Tm[6], T13 = Tm[7];

    // ---- decode 8 boxes: b = p*2 + a  (p = pixel-in-quad, a = anchor) ----
    float px1[8], py1[8], px2[8], py2[8], areat[8], wlog[8];

#pragma unroll
    for (int p = 0; p < 4; p++) {
        const float ay = fmaf((float)(jq * 4 + p), dys, y0);
#pragma unroll
        for (int a = 0; a < 2; a++) {
            const int b = p * 2 + a;

            float xl = f4c((a == 0) ? sA : sB, p);
            wlog[b] = (xl > LOGIT_THRESH)
                        ? -__logf(1.0f + __expf(xl)) : 0.0f;

            float d0 = f4c(rc[a * 7 + 0], p);
            float d1 = f4c(rc[a * 7 + 1], p);
            float d2 = f4c(rc[a * 7 + 2], p);
            float d3 = f4c(rc[a * 7 + 3], p);
            float d4 = f4c(rc[a * 7 + 4], p);
            float d5 = f4c(rc[a * 7 + 5], p);
            float d6 = f4c(rc[a * 7 + 6], p);

            float X = fmaf(d0, dg, ax);
            float Y = fmaf(d1, dg, ay);
            float Z = fmaf(d2, ah, cz);
            float hh = __expf(d3) * ah;
            float ww = __expf(d4) * aw;
            float ll = __expf(d5) * al;

            float c, s;
            __sincosf(d6 + ((a == 0) ? yaw0 : yaw1), &s, &c);

            float bx = fmaf(T00, X, fmaf(T01, Y, fmaf(T02, Z, T03)));
            float by = fmaf(T10, X, fmaf(T11, Y, fmaf(T12, Z, T13)));
            float ex = 0.5f * (fabsf(fmaf(T00, c,  T01 * s)) * ll +
                               fabsf(fmaf(T01, c, -T00 * s)) * ww +
                               fabsf(T02) * hh);
            float ey = 0.5f * (fabsf(fmaf(T10, c,  T11 * s)) * ll +
                               fabsf(fmaf(T11, c, -T10 * s)) * ww +
                               fabsf(T12) * hh);

            px1[b] = bx - ex;  px2[b] = bx + ex;
            py1[b] = by - ey;  py2[b] = by + ey;
            areat[b] = (2.0f * ex) * (2.0f * ey);
        }
    }

    // ---- block bounding box over all 8 boxes per thread ----
    float bminx = px1[0], bminy = py1[0], bmaxx = px2[0], bmaxy = py2[0];
#pragma unroll
    for (int b = 1; b < 8; b++) {
        bminx = fminf(bminx, px1[b]);  bminy = fminf(bminy, py1[b]);
        bmaxx = fmaxf(bmaxx, px2[b]);  bmaxy = fmaxf(bmaxy, py2[b]);
    }

    __shared__ float s_minx[8], s_miny[8], s_maxx[8], s_maxy[8];
    __shared__ float s_bbox[4];
#pragma unroll
    for (int off = 16; off > 0; off >>= 1) {
        bminx = fminf(bminx, __shfl_xor_sync(0xFFFFFFFFu, bminx, off));
        bminy = fminf(bminy, __shfl_xor_sync(0xFFFFFFFFu, bminy, off));
        bmaxx = fmaxf(bmaxx, __shfl_xor_sync(0xFFFFFFFFu, bmaxx, off));
        bmaxy = fmaxf(bmaxy, __shfl_xor_sync(0xFFFFFFFFu, bmaxy, off));
    }
    const int lane = tid & 31;
    const int wid  = tid >> 5;
    if (lane == 0) {
        s_minx[wid] = bminx;  s_miny[wid] = bminy;
        s_maxx[wid] = bmaxx;  s_maxy[wid] = bmaxy;
    }
    __syncthreads();
    if (wid == 0) {
        float m0 = (lane < 8) ? s_minx[lane] :  1e30f;
        float m1 = (lane < 8) ? s_miny[lane] :  1e30f;
        float m2 = (lane < 8) ? s_maxx[lane] : -1e30f;
        float m3 = (lane < 8) ? s_maxy[lane] : -1e30f;
#pragma unroll
        for (int off = 4; off > 0; off >>= 1) {
            m0 = fminf(m0, __shfl_xor_sync(0xFFFFFFFFu, m0, off));
            m1 = fminf(m1, __shfl_xor_sync(0xFFFFFFFFu, m1, off));
            m2 = fmaxf(m2, __shfl_xor_sync(0xFFFFFFFFu, m2, off));
            m3 = fmaxf(m3, __shfl_xor_sync(0xFFFFFFFFu, m3, off));
        }
        if (lane == 0) {
            s_bbox[0] = m0;  s_bbox[1] = m1;  s_bbox[2] = m2;  s_bbox[3] = m3;
        }
    }
    __syncthreads();

    // ---- cull targets against block bbox ----
    __shared__ int    s_cnt;
    __shared__ float4 s_cbox[NTGT];
    __shared__ float  s_carea[NTGT];
    if (tid == 0) s_cnt = 0;
    __syncthreads();
    if (tid < NTGT) {
        bool hit = (tminx <= s_bbox[2]) && (tmaxx >= s_bbox[0]) &&
                   (tminy <= s_bbox[3]) && (tmaxy >= s_bbox[1]);
        if (hit) {
            int idx = atomicAdd(&s_cnt, 1);
            s_cbox[idx]  = make_float4(tminx, tminy, tmaxx, tmaxy);
            s_carea[idx] = tarea;
        }
    }
    __syncthreads();
    const int cnt = s_cnt;

    // ---- IoU over survivors for all 8 boxes ----
    float acc[8] = {0.f, 0.f, 0.f, 0.f, 0.f, 0.f, 0.f, 0.f};
    for (int m = 0; m < cnt; m++) {
        const float4 tb = s_cbox[m];
        const float  ta = s_carea[m];
#pragma unroll
        for (int b = 0; b < 8; b++) {
            float wi = fminf(px2[b], tb.z) - fmaxf(px1[b], tb.x);
            float hi = fminf(py2[b], tb.w) - fmaxf(py1[b], tb.y);
            if (wi > 0.0f && hi > 0.0f) {
                float wh = wi * hi;
                acc[b] += __fdividef(wh, areat[b] + ta - wh);
            }
        }
    }

    float local = 0.0f;
#pragma unroll
    for (int b = 0; b < 8; b++) local += wlog[b] * acc[b];

    // ---- block sum -> atomic scalar accumulate; last block publishes ----
    __shared__ float red[8];
#pragma unroll
    for (int off = 16; off > 0; off >>= 1)
        local += __shfl_down_sync(0xFFFFFFFFu, local, off);
    if (lane == 0) red[wid] = local;
    __syncthreads();
    if (wid == 0) {
        float v = (lane < 8) ? red[lane] : 0.0f;
#pragma unroll
        for (int off = 4; off > 0; off >>= 1)
            v += __shfl_down_sync(0xFFFFFFFFu, v, off);
        if (lane == 0) {
            atomicAdd(&g_accum, v);
            __threadfence();                       // order accum before ticket
            unsigned int t = atomicAdd(&g_done, 1u);
            if (t == NBLK - 1) {
                float total = atomicAdd(&g_accum, 0.0f);
                out[0] = total;
                g_accum = 0.0f;                    // reset for next replay
                g_done  = 0u;
            }
        }
    }
}

extern "C" void kernel_launch(void* const* d_in, const int* in_sizes, int n_in,
                              void* d_out, int out_size) {
    const float* psm = (const float*)d_in[0];
    const float* rm  = (const float*)d_in[1];
    const float* anc = (const float*)d_in[2];
    const float* Tm  = (const float*)d_in[3];
    const float* tgt = (const float*)d_in[4];
    float* out = (float*)d_out;

    loss_kernel<<<NBLK, TPB>>>(psm, rm, anc, Tm, tgt, out);
}